// round 1
// baseline (speedup 1.0000x reference)
#include <cuda_runtime.h>

#define NPATCH 196
#define NTHREADS 256

// CNOT: for amplitudes with ctrl bit set, flip target bit (register swap; free after unroll)
#define CNOT(cw, tw) { \
    const int cb = 1 << (3 - (cw)), tb = 1 << (3 - (tw)); \
    _Pragma("unroll") \
    for (int i = 0; i < 16; i++) { \
        if ((i & cb) && !(i & tb)) { float tmp = st[i]; st[i] = st[i | tb]; st[i | tb] = tmp; } \
    } }

// Ry on wire w with cos/sin of half-angle
#define RYW(w, cv, sv) { \
    const int bb = 1 << (3 - (w)); \
    _Pragma("unroll") \
    for (int i = 0; i < 16; i++) { \
        if (!(i & bb)) { \
            float a0 = st[i], a1 = st[i | bb]; \
            st[i]      = (cv) * a0 - (sv) * a1; \
            st[i | bb] = (sv) * a0 + (cv) * a1; \
        } \
    } }

__global__ __launch_bounds__(NTHREADS)
void quanv_kernel(const float* __restrict__ x,
                  const float* __restrict__ params,
                  const float* __restrict__ W,
                  const float* __restrict__ bias,
                  float* __restrict__ out)
{
    __shared__ float img[784];
    __shared__ float p0s[4];            // layer-0 raw params (fused into encoding angle)
    __shared__ float c2s[4], s2s[4];    // layer-1 cos/sin of half-angle
    __shared__ float wsum[8][10];
    __shared__ float slogits[10];

    const int b = blockIdx.x;
    const int t = threadIdx.x;

    // Cooperative coalesced image load
    const float* xb = x + b * 784;
    #pragma unroll
    for (int i = t; i < 784; i += NTHREADS) img[i] = xb[i];

    if (t < 4) {
        p0s[t] = params[t];
        float sv, cv;
        __sincosf(params[4 + t] * 0.5f, &sv, &cv);
        c2s[t] = cv; s2s[t] = sv;
    }
    __syncthreads();

    float partial[10];
    #pragma unroll
    for (int c = 0; c < 10; c++) partial[c] = 0.0f;

    if (t < NPATCH) {
        const int pr = t / 14, pc = t % 14;
        const float* base = img + (2 * pr) * 28 + 2 * pc;
        // angle order k = a*2 + c : (row offset a, col offset c)
        float ang0 = base[0], ang1 = base[1], ang2 = base[28], ang3 = base[29];

        float cc[4], ss[4];
        __sincosf((ang0 + p0s[0]) * 0.5f, &ss[0], &cc[0]);
        __sincosf((ang1 + p0s[1]) * 0.5f, &ss[1], &cc[1]);
        __sincosf((ang2 + p0s[2]) * 0.5f, &ss[2], &cc[2]);
        __sincosf((ang3 + p0s[3]) * 0.5f, &ss[3], &cc[3]);

        // Product state after encoding + layer-0 Rys (fused): idx = q0<<3 | q1<<2 | q2<<1 | q3
        float a01[4] = { cc[0]*cc[1], cc[0]*ss[1], ss[0]*cc[1], ss[0]*ss[1] };
        float a23[4] = { cc[2]*cc[3], cc[2]*ss[3], ss[2]*cc[3], ss[2]*ss[3] };
        float st[16];
        #pragma unroll
        for (int u = 0; u < 4; u++) {
            #pragma unroll
            for (int v = 0; v < 4; v++) st[u * 4 + v] = a01[u] * a23[v];
        }

        // layer 0 entanglers
        CNOT(0, 1); CNOT(1, 2); CNOT(2, 3); CNOT(3, 0);
        // layer 1 rotations
        RYW(0, c2s[0], s2s[0]);
        RYW(1, c2s[1], s2s[1]);
        RYW(2, c2s[2], s2s[2]);
        RYW(3, c2s[3], s2s[3]);
        // layer 1 entanglers
        CNOT(0, 1); CNOT(1, 2); CNOT(2, 3); CNOT(3, 0);

        // Measurement: PauliZ expvals via signed butterfly over probabilities
        float pp[16];
        #pragma unroll
        for (int i = 0; i < 16; i++) pp[i] = st[i] * st[i];

        float ap[8], am[8];
        #pragma unroll
        for (int j = 0; j < 8; j++) { ap[j] = pp[2*j] + pp[2*j+1]; am[j] = pp[2*j] - pp[2*j+1]; }
        float z3 = ((am[0] + am[1]) + (am[2] + am[3])) + ((am[4] + am[5]) + (am[6] + am[7]));

        float bp[4], bm[4];
        #pragma unroll
        for (int k = 0; k < 4; k++) { bp[k] = ap[2*k] + ap[2*k+1]; bm[k] = ap[2*k] - ap[2*k+1]; }
        float z2 = (bm[0] + bm[1]) + (bm[2] + bm[3]);

        float cp0 = bp[0] + bp[1], cp1 = bp[2] + bp[3];
        float z1 = (bp[0] - bp[1]) + (bp[2] - bp[3]);
        float z0 = cp0 - cp1;

        // Per-patch linear partials: feat f = 4*t + wire; W row-major [10, 784]
        #pragma unroll
        for (int c = 0; c < 10; c++) {
            const float4 wv = *reinterpret_cast<const float4*>(W + c * 784 + 4 * t);
            partial[c] = fmaf(z0, wv.x, fmaf(z1, wv.y, fmaf(z2, wv.z, z3 * wv.w)));
        }
    }

    // Block reduction: warp shuffle then cross-warp via smem
    #pragma unroll
    for (int c = 0; c < 10; c++) {
        float v = partial[c];
        #pragma unroll
        for (int off = 16; off > 0; off >>= 1)
            v += __shfl_down_sync(0xffffffffu, v, off);
        if ((t & 31) == 0) wsum[t >> 5][c] = v;
    }
    __syncthreads();

    if (t < 10) {
        float v = bias[t];
        #pragma unroll
        for (int w = 0; w < 8; w++) v += wsum[w][t];
        slogits[t] = v;
    }
    __syncthreads();

    if (t < 10) {
        float m = slogits[0];
        #pragma unroll
        for (int c = 1; c < 10; c++) m = fmaxf(m, slogits[c]);
        float se = 0.0f;
        #pragma unroll
        for (int c = 0; c < 10; c++) se += __expf(slogits[c] - m);
        out[b * 10 + t] = slogits[t] - m - __logf(se);
    }
}

extern "C" void kernel_launch(void* const* d_in, const int* in_sizes, int n_in,
                              void* d_out, int out_size) {
    const float* x      = (const float*)d_in[0];   // [8192, 28, 28]
    const float* params = (const float*)d_in[1];   // [2, 4]
    const float* W      = (const float*)d_in[2];   // [10, 784]
    const float* bias   = (const float*)d_in[3];   // [10]
    float* out          = (float*)d_out;           // [8192, 10]

    const int B = in_sizes[0] / 784;
    quanv_kernel<<<B, NTHREADS>>>(x, params, W, bias, out);
}